// round 1
// baseline (speedup 1.0000x reference)
#include <cuda_runtime.h>
#include <math.h>
#include <float.h>

#define BATCH 2
#define NTOK  8000
#define CDIM  512
#define NSR   1000
#define NHEADS 8
#define HD    64

// ---------------- scratch (device globals: no allocation allowed) ----------------
__device__ float g_xr[BATCH * NSR * CDIM];          // 4 MB
__device__ float g_kv[BATCH * NSR * 2 * CDIM];      // 8 MB  (cols 0..511 = K, 512..1023 = V)
__device__ float g_q [BATCH * NTOK * CDIM];         // 33 MB
__device__ float g_o [BATCH * NTOK * CDIM];         // 33 MB
__device__ float g_y [BATCH * NTOK * CDIM];         // 33 MB

// ---------------- kernel 1: depthwise conv3d (3,s2,p1) + bias + LayerNorm ----------------
__global__ void __launch_bounds__(256) conv_ln_kernel(
    const float* __restrict__ x, const float* __restrict__ srw,
    const float* __restrict__ srb, const float* __restrict__ g,
    const float* __restrict__ beta, float* __restrict__ xr)
{
    int bp = blockIdx.x;
    int b = bp / NSR;
    int opos = bp % NSR;
    int od = opos / 100, oh = (opos / 10) % 10, ow = opos % 10;

    __shared__ float vals[CDIM];
    __shared__ float red[18];

    float loc[2];
#pragma unroll
    for (int ci = 0; ci < 2; ci++) {
        int c = threadIdx.x + ci * 256;
        float acc = srb[c];
#pragma unroll
        for (int kd = 0; kd < 3; kd++) {
            int id = od * 2 - 1 + kd;
            if ((unsigned)id >= 20u) continue;
#pragma unroll
            for (int kh = 0; kh < 3; kh++) {
                int ih = oh * 2 - 1 + kh;
                if ((unsigned)ih >= 20u) continue;
#pragma unroll
                for (int kw = 0; kw < 3; kw++) {
                    int iw = ow * 2 - 1 + kw;
                    if ((unsigned)iw >= 20u) continue;
                    int n = id * 400 + ih * 20 + iw;
                    acc += x[((size_t)b * NTOK + n) * CDIM + c] *
                           srw[c * 27 + kd * 9 + kh * 3 + kw];
                }
            }
        }
        vals[c] = acc;
        loc[ci] = acc;
    }
    float s  = loc[0] + loc[1];
    float sq = loc[0] * loc[0] + loc[1] * loc[1];
#pragma unroll
    for (int o2 = 16; o2 > 0; o2 >>= 1) {
        s  += __shfl_down_sync(0xffffffffu, s,  o2);
        sq += __shfl_down_sync(0xffffffffu, sq, o2);
    }
    int w = threadIdx.x >> 5;
    if ((threadIdx.x & 31) == 0) { red[w] = s; red[8 + w] = sq; }
    __syncthreads();
    if (threadIdx.x == 0) {
        float a = 0.f, b2 = 0.f;
        for (int i = 0; i < 8; i++) { a += red[i]; b2 += red[8 + i]; }
        red[16] = a; red[17] = b2;
    }
    __syncthreads();
    float mean = red[16] * (1.f / CDIM);
    float var  = red[17] * (1.f / CDIM) - mean * mean;
    float inv  = rsqrtf(var + 1e-6f);
#pragma unroll
    for (int ci = 0; ci < 2; ci++) {
        int c = threadIdx.x + ci * 256;
        xr[((size_t)b * NSR + opos) * CDIM + c] = (vals[c] - mean) * inv * g[c] + beta[c];
    }
}

// ---------------- generic GEMM + bias: C[M,N] = A[M,K] @ B[K,N] + bias ----------------
// 128x128 block tile, BK=16, 256 threads, 8x8 micro-tile
__global__ void __launch_bounds__(256) gemm_bias_kernel(
    const float* __restrict__ A, const float* __restrict__ B,
    const float* __restrict__ bias, float* __restrict__ C,
    int M, int N, int K)
{
    __shared__ float As[16][128];
    __shared__ float Bs[16][128];

    int tid = threadIdx.x;
    int tx = tid & 15, ty = tid >> 4;
    int rowBase = blockIdx.y * 128, colBase = blockIdx.x * 128;

    float acc[8][8];
#pragma unroll
    for (int i = 0; i < 8; i++)
#pragma unroll
        for (int j = 0; j < 8; j++) acc[i][j] = 0.f;

    for (int kt = 0; kt < K; kt += 16) {
#pragma unroll
        for (int l = 0; l < 2; l++) {
            int idx = tid + l * 256;
            int r = idx >> 2, kc = (idx & 3) << 2;
            int gr = rowBase + r;
            float4 v = make_float4(0.f, 0.f, 0.f, 0.f);
            if (gr < M) v = *(const float4*)&A[(size_t)gr * K + kt + kc];
            As[kc + 0][r] = v.x; As[kc + 1][r] = v.y;
            As[kc + 2][r] = v.z; As[kc + 3][r] = v.w;
        }
#pragma unroll
        for (int l = 0; l < 2; l++) {
            int idx = tid + l * 256;
            int kr = idx >> 5, cc = (idx & 31) << 2;
            *(float4*)&Bs[kr][cc] = *(const float4*)&B[(size_t)(kt + kr) * N + colBase + cc];
        }
        __syncthreads();
#pragma unroll
        for (int k = 0; k < 16; k++) {
            float a[8], bb[8];
            *(float4*)&a[0]  = *(float4*)&As[k][ty * 8];
            *(float4*)&a[4]  = *(float4*)&As[k][ty * 8 + 4];
            *(float4*)&bb[0] = *(float4*)&Bs[k][tx * 8];
            *(float4*)&bb[4] = *(float4*)&Bs[k][tx * 8 + 4];
#pragma unroll
            for (int i = 0; i < 8; i++)
#pragma unroll
                for (int j = 0; j < 8; j++) acc[i][j] += a[i] * bb[j];
        }
        __syncthreads();
    }
#pragma unroll
    for (int i = 0; i < 8; i++) {
        int gr = rowBase + ty * 8 + i;
        if (gr < M) {
#pragma unroll
            for (int j = 0; j < 8; j++) {
                int gc = colBase + tx * 8 + j;
                C[(size_t)gr * N + gc] = acc[i][j] + bias[gc];
            }
        }
    }
}

// ---------------- kernel 4: flash attention (fp32) ----------------
// grid: (N/64, B*h). block 256. Tiles: Q 64x64, K 64x64, V 64x64, P 64x64 in smem.
#define ATT_STRIDE 68
#define ATT_SMEM_FLOATS (4 * 64 * ATT_STRIDE + 3 * 64)
#define ATT_SMEM_BYTES  (ATT_SMEM_FLOATS * 4)

__global__ void __launch_bounds__(256) attn_kernel(
    const float* __restrict__ q, const float* __restrict__ kv,
    float* __restrict__ o)
{
    extern __shared__ float sm[];
    float (*Qs)[ATT_STRIDE] = (float(*)[ATT_STRIDE])(sm);
    float (*Ks)[ATT_STRIDE] = (float(*)[ATT_STRIDE])(sm + 64 * ATT_STRIDE);
    float (*Vs)[ATT_STRIDE] = (float(*)[ATT_STRIDE])(sm + 2 * 64 * ATT_STRIDE);
    float (*Ps)[ATT_STRIDE] = (float(*)[ATT_STRIDE])(sm + 3 * 64 * ATT_STRIDE);
    float* rowM = sm + 4 * 64 * ATT_STRIDE;
    float* rowL = rowM + 64;
    float* rowC = rowL + 64;

    int tid = threadIdx.x;
    int tx = tid & 15, ty = tid >> 4;
    int bh = blockIdx.y;
    int b = bh >> 3, h = bh & 7;
    int qbase = blockIdx.x * 64;
    size_t qoff   = ((size_t)b * NTOK + qbase) * CDIM + h * HD;
    size_t kvbase = (size_t)b * NSR * 1024 + h * HD;

    // load Q tile (64 rows x 64 dims)
#pragma unroll
    for (int l = 0; l < 4; l++) {
        int idx = tid + l * 256;
        int i = idx >> 4, d4 = (idx & 15) << 2;
        *(float4*)&Qs[i][d4] = *(const float4*)&q[qoff + (size_t)i * CDIM + d4];
    }
    if (tid < 64) { rowM[tid] = -FLT_MAX; rowL[tid] = 0.f; }

    float acc[4][4];
#pragma unroll
    for (int i = 0; i < 4; i++)
#pragma unroll
        for (int j = 0; j < 4; j++) acc[i][j] = 0.f;

    const float scale = 0.125f;  // 64^-0.5

    for (int kb = 0; kb < NSR; kb += 64) {
        __syncthreads();  // protect Ks/Vs/Ps from prior-iteration readers
#pragma unroll
        for (int l = 0; l < 4; l++) {
            int idx = tid + l * 256;
            int m = idx >> 4, d4 = (idx & 15) << 2;
            int gm = kb + m;
            float4 kf = make_float4(0.f, 0.f, 0.f, 0.f);
            float4 vf = make_float4(0.f, 0.f, 0.f, 0.f);
            if (gm < NSR) {
                kf = *(const float4*)&kv[kvbase + (size_t)gm * 1024 + d4];
                vf = *(const float4*)&kv[kvbase + (size_t)gm * 1024 + 512 + d4];
            }
            *(float4*)&Ks[m][d4] = kf;
            *(float4*)&Vs[m][d4] = vf;
        }
        __syncthreads();

        // S = Q @ K^T  (4x4 micro-tile, k unrolled by 4 via float4 fragments)
        float s4[4][4];
#pragma unroll
        for (int i = 0; i < 4; i++)
#pragma unroll
            for (int j = 0; j < 4; j++) s4[i][j] = 0.f;

#pragma unroll
        for (int k4 = 0; k4 < 64; k4 += 4) {
            float4 qf[4], kf[4];
#pragma unroll
            for (int i = 0; i < 4; i++) qf[i] = *(float4*)&Qs[ty * 4 + i][k4];
#pragma unroll
            for (int j = 0; j < 4; j++) kf[j] = *(float4*)&Ks[tx * 4 + j][k4];
#pragma unroll
            for (int i = 0; i < 4; i++)
#pragma unroll
                for (int j = 0; j < 4; j++)
                    s4[i][j] += qf[i].x * kf[j].x + qf[i].y * kf[j].y +
                                qf[i].z * kf[j].z + qf[i].w * kf[j].w;
        }
#pragma unroll
        for (int i = 0; i < 4; i++)
#pragma unroll
            for (int j = 0; j < 4; j++)
                Ps[ty * 4 + i][tx * 4 + j] = s4[i][j] * scale;
        __syncthreads();

        // online softmax row pass (one thread per row)
        if (tid < 64) {
            int valid = NSR - kb; if (valid > 64) valid = 64;
            float mOld = rowM[tid];
            float tm = -FLT_MAX;
            for (int j = 0; j < valid; j++) tm = fmaxf(tm, Ps[tid][j]);
            float nm = fmaxf(mOld, tm);
            float corr = __expf(mOld - nm);   // first tile: exp(-inf) = 0
            float ssum = 0.f;
            for (int j = 0; j < 64; j++) {
                float p = (j < valid) ? __expf(Ps[tid][j] - nm) : 0.f;
                Ps[tid][j] = p;
                ssum += p;
            }
            rowL[tid] = rowL[tid] * corr + ssum;
            rowM[tid] = nm;
            rowC[tid] = corr;
        }
        __syncthreads();

        // rescale accumulator, then O += P @ V
#pragma unroll
        for (int i = 0; i < 4; i++) {
            float cr = rowC[ty * 4 + i];
#pragma unroll
            for (int j = 0; j < 4; j++) acc[i][j] *= cr;
        }
#pragma unroll
        for (int m4 = 0; m4 < 64; m4 += 4) {
            float pfa[4][4];
            float vfa[4][4];
#pragma unroll
            for (int i = 0; i < 4; i++) {
                float4 p4 = *(float4*)&Ps[ty * 4 + i][m4];
                pfa[i][0] = p4.x; pfa[i][1] = p4.y; pfa[i][2] = p4.z; pfa[i][3] = p4.w;
            }
#pragma unroll
            for (int u = 0; u < 4; u++) {
                float4 v4 = *(float4*)&Vs[m4 + u][tx * 4];
                vfa[u][0] = v4.x; vfa[u][1] = v4.y; vfa[u][2] = v4.z; vfa[u][3] = v4.w;
            }
#pragma unroll
            for (int i = 0; i < 4; i++)
#pragma unroll
                for (int u = 0; u < 4; u++)
#pragma unroll
                    for (int j = 0; j < 4; j++)
                        acc[i][j] += pfa[i][u] * vfa[u][j];
        }
    }

    // finalize
#pragma unroll
    for (int i = 0; i < 4; i++) {
        int r = ty * 4 + i;
        float invl = 1.f / rowL[r];
        int gn = qbase + r;
#pragma unroll
        for (int j = 0; j < 4; j++)
            o[((size_t)b * NTOK + gn) * CDIM + h * HD + tx * 4 + j] = acc[i][j] * invl;
    }
}

// ---------------- kernel 5: trilinear upsample of V + LayerNorm + add o ----------------
__global__ void __launch_bounds__(256) ups_ln_add_kernel(
    const float* __restrict__ kv, const float* __restrict__ ob,
    const float* __restrict__ g, const float* __restrict__ beta,
    float* __restrict__ y)
{
    int bn = blockIdx.x;
    int b = bn / NTOK, n = bn % NTOK;
    int d = n / 400, hh = (n / 20) % 20, ww = n % 20;

    // half-pixel trilinear, edge-clamped (matches jax.image.resize weight renorm)
    float sd = d  * 0.5f - 0.25f; int fd = (int)floorf(sd); float wdz = sd - (float)fd;
    float sh = hh * 0.5f - 0.25f; int fh = (int)floorf(sh); float why = sh - (float)fh;
    float sw = ww * 0.5f - 0.25f; int fw = (int)floorf(sw); float wwx = sw - (float)fw;
    int dz0 = fd < 0 ? 0 : fd;        int dz1 = (fd + 1) > 9 ? 9 : (fd + 1);
    int hy0 = fh < 0 ? 0 : fh;        int hy1 = (fh + 1) > 9 ? 9 : (fh + 1);
    int wx0 = fw < 0 ? 0 : fw;        int wx1 = (fw + 1) > 9 ? 9 : (fw + 1);

    int   midx[8];
    float wt8[8];
    {
        int zzv[2] = {dz0, dz1};  float wzv[2] = {1.f - wdz, wdz};
        int yyv[2] = {hy0, hy1};  float wyv[2] = {1.f - why, why};
        int xxv[2] = {wx0, wx1};  float wxv[2] = {1.f - wwx, wwx};
        int t = 0;
#pragma unroll
        for (int a = 0; a < 2; a++)
#pragma unroll
            for (int b2 = 0; b2 < 2; b2++)
#pragma unroll
                for (int c2 = 0; c2 < 2; c2++) {
                    midx[t] = zzv[a] * 100 + yyv[b2] * 10 + xxv[c2];
                    wt8[t]  = wzv[a] * wyv[b2] * wxv[c2];
                    t++;
                }
    }

    __shared__ float vals[CDIM];
    __shared__ float red[18];
    size_t kvb = (size_t)b * NSR * 1024 + 512;   // V half

    float loc[2];
#pragma unroll
    for (int ci = 0; ci < 2; ci++) {
        int c = threadIdx.x + ci * 256;
        float acc = 0.f;
#pragma unroll
        for (int t = 0; t < 8; t++)
            acc += wt8[t] * kv[kvb + (size_t)midx[t] * 1024 + c];
        vals[c] = acc;
        loc[ci] = acc;
    }
    float s  = loc[0] + loc[1];
    float sq = loc[0] * loc[0] + loc[1] * loc[1];
#pragma unroll
    for (int o2 = 16; o2 > 0; o2 >>= 1) {
        s  += __shfl_down_sync(0xffffffffu, s,  o2);
        sq += __shfl_down_sync(0xffffffffu, sq, o2);
    }
    int w = threadIdx.x >> 5;
    if ((threadIdx.x & 31) == 0) { red[w] = s; red[8 + w] = sq; }
    __syncthreads();
    if (threadIdx.x == 0) {
        float a = 0.f, b2 = 0.f;
        for (int i = 0; i < 8; i++) { a += red[i]; b2 += red[8 + i]; }
        red[16] = a; red[17] = b2;
    }
    __syncthreads();
    float mean = red[16] * (1.f / CDIM);
    float var  = red[17] * (1.f / CDIM) - mean * mean;
    float inv  = rsqrtf(var + 1e-6f);
#pragma unroll
    for (int ci = 0; ci < 2; ci++) {
        int c = threadIdx.x + ci * 256;
        size_t oidx = ((size_t)b * NTOK + n) * CDIM + c;
        float idn = (vals[c] - mean) * inv * g[c] + beta[c];
        y[oidx] = ob[oidx] + idn;
    }
}

// ---------------- launch ----------------
extern "C" void kernel_launch(void* const* d_in, const int* in_sizes, int n_in,
                              void* d_out, int out_size)
{
    const float* x      = (const float*)d_in[0];
    const float* Wq     = (const float*)d_in[1];
    const float* bq     = (const float*)d_in[2];
    const float* Wkv    = (const float*)d_in[3];
    const float* bkv    = (const float*)d_in[4];
    const float* srw    = (const float*)d_in[5];
    const float* srb    = (const float*)d_in[6];
    const float* srg    = (const float*)d_in[7];
    const float* srbeta = (const float*)d_in[8];
    const float* upg    = (const float*)d_in[9];
    const float* upbeta = (const float*)d_in[10];
    const float* Wp     = (const float*)d_in[11];
    const float* bp     = (const float*)d_in[12];
    float* out = (float*)d_out;

    float *xr, *kvb, *qb, *ob, *yb;
    cudaGetSymbolAddress((void**)&xr,  g_xr);
    cudaGetSymbolAddress((void**)&kvb, g_kv);
    cudaGetSymbolAddress((void**)&qb,  g_q);
    cudaGetSymbolAddress((void**)&ob,  g_o);
    cudaGetSymbolAddress((void**)&yb,  g_y);

    cudaFuncSetAttribute(attn_kernel, cudaFuncAttributeMaxDynamicSharedMemorySize,
                         ATT_SMEM_BYTES);

    // 1. conv + LN -> xr
    conv_ln_kernel<<<BATCH * NSR, 256>>>(x, srw, srb, srg, srbeta, xr);

    // 2. kv = xr @ Wkv + bkv   (2000 x 1024 x 512)
    gemm_bias_kernel<<<dim3(1024 / 128, (BATCH * NSR + 127) / 128), 256>>>(
        xr, Wkv, bkv, kvb, BATCH * NSR, 1024, CDIM);

    // 3. q = x @ Wq + bq       (16000 x 512 x 512)
    gemm_bias_kernel<<<dim3(CDIM / 128, (BATCH * NTOK) / 128), 256>>>(
        x, Wq, bq, qb, BATCH * NTOK, CDIM, CDIM);

    // 4. attention -> o
    attn_kernel<<<dim3(NTOK / 64, BATCH * NHEADS), 256, ATT_SMEM_BYTES>>>(qb, kvb, ob);

    // 5. upsample(V) + LN + add o -> y
    ups_ln_add_kernel<<<BATCH * NTOK, 256>>>(kvb, ob, upg, upbeta, yb);

    // 6. out = y @ Wp + bp     (16000 x 512 x 512)
    gemm_bias_kernel<<<dim3(CDIM / 128, (BATCH * NTOK) / 128), 256>>>(
        yb, Wp, bp, out, BATCH * NTOK, CDIM, CDIM);
}